// round 1
// baseline (speedup 1.0000x reference)
#include <cuda_runtime.h>

// out[n] = (deg_in(n) > 0 ? x[n] @ (Wo@Wv)^T : 0) + bo
// (softmax weights over each tgt-segment sum to 1 and multiply V[tgt],
//  so the whole attention collapses; see analysis.)

#define DIM 128

// Scratch (no allocations allowed): combined matrix, transposed for GEMM B, and node mask.
__device__ float g_Mt[DIM * DIM];            // Mt[k][i] = sum_j Wo[i][j] * Wv[j][k]
__device__ unsigned char g_mask[131072];     // N = 50000 fits

// ---------------------------------------------------------------------------
// Kernel 1: Mt = (Wo @ Wv)^T  and clear mask.
// grid = 128 blocks, block = 128 threads. Block i computes Mc row i (= Mt col i).
// ---------------------------------------------------------------------------
__global__ void prep_kernel(const float* __restrict__ Wo,
                            const float* __restrict__ Wv,
                            int N) {
    __shared__ float wo_row[DIM];
    const int i = blockIdx.x;    // row of Mc = Wo@Wv
    const int j = threadIdx.x;   // col of Mc
    wo_row[j] = Wo[i * DIM + j];
    __syncthreads();

    float acc = 0.0f;
#pragma unroll 16
    for (int k = 0; k < DIM; ++k)
        acc = fmaf(wo_row[k], Wv[k * DIM + j], acc);
    g_Mt[j * DIM + i] = acc;     // transposed store: Mt[k=j][i]

    // clear mask (grid-stride over N)
    for (int n = blockIdx.x * DIM + j; n < N; n += gridDim.x * DIM)
        g_mask[n] = 0;
}

// ---------------------------------------------------------------------------
// Kernel 2: mask[tgt[e]] = 1. Races write the same value -> benign.
// ---------------------------------------------------------------------------
__global__ void mask_kernel(const int* __restrict__ tgt, int E) {
    int e = blockIdx.x * blockDim.x + threadIdx.x;
    if (e < E)
        g_mask[tgt[e]] = 1;
}

// ---------------------------------------------------------------------------
// Kernel 3: out[n,:] = mask[n] ? x[n] @ Mt + bo : bo
// Classic 128x128 block tile, 256 threads, 8x8 micro-tile (split 4+4 rows/cols).
// B (=Mt, 64KB) loaded to smem once; A streamed in BK=16 chunks, transposed.
// ---------------------------------------------------------------------------
#define BK 16
#define SMEM_FLOATS (DIM * DIM + BK * DIM + DIM)   // Bs + As + bo
#define SMEM_BYTES  (SMEM_FLOATS * 4)

__global__ __launch_bounds__(256) void out_kernel(const float* __restrict__ X,
                                                  const float* __restrict__ bo,
                                                  float* __restrict__ out,
                                                  int N) {
    extern __shared__ float sm[];
    float* Bs  = sm;                 // [128][128]  Mt[k][i]
    float* As  = sm + DIM * DIM;     // [BK][128]   x tile, transposed (k-major)
    float* boS = As + BK * DIM;      // [128]

    const int tid = threadIdx.x;
    const int tx  = tid % 16;        // col group
    const int ty  = tid / 16;        // row group
    const int row0 = blockIdx.x * DIM;

    // Load Mt into shared (4096 float4 / 256 threads = 16 each)
    {
        const float4* Bg = (const float4*)g_Mt;
        float4* Bs4 = (float4*)Bs;
#pragma unroll
        for (int i = tid; i < (DIM * DIM) / 4; i += 256)
            Bs4[i] = Bg[i];
    }
    if (tid < DIM) boS[tid] = bo[tid];

    float acc[8][8];
#pragma unroll
    for (int i = 0; i < 8; ++i)
#pragma unroll
        for (int j = 0; j < 8; ++j) acc[i][j] = 0.0f;

    for (int k0 = 0; k0 < DIM; k0 += BK) {
        __syncthreads();   // protect previous As use, and (first iter) Bs/boS fill
        // Load A tile rows row0..row0+127, cols k0..k0+15; store transposed As[k][m].
        // 512 float4 per chunk / 256 threads = 2 each. 4 lanes cover one row (64B).
#pragma unroll
        for (int f = tid; f < (DIM * BK) / 4; f += 256) {
            int r  = f >> 2;            // row within tile
            int kq = (f & 3) << 2;      // k offset within chunk (0,4,8,12)
            float4 v = make_float4(0.f, 0.f, 0.f, 0.f);
            int grow = row0 + r;
            if (grow < N)
                v = *(const float4*)&X[grow * DIM + k0 + kq];
            As[(kq + 0) * DIM + r] = v.x;
            As[(kq + 1) * DIM + r] = v.y;
            As[(kq + 2) * DIM + r] = v.z;
            As[(kq + 3) * DIM + r] = v.w;
        }
        __syncthreads();

#pragma unroll
        for (int k = 0; k < BK; ++k) {
            const float* Ak = &As[k * DIM];
            const float* Bk = &Bs[(k0 + k) * DIM];
            float4 a0 = *(const float4*)&Ak[4 * ty];
            float4 a1 = *(const float4*)&Ak[64 + 4 * ty];
            float4 b0 = *(const float4*)&Bk[4 * tx];
            float4 b1 = *(const float4*)&Bk[64 + 4 * tx];
            float a[8] = {a0.x, a0.y, a0.z, a0.w, a1.x, a1.y, a1.z, a1.w};
            float b[8] = {b0.x, b0.y, b0.z, b0.w, b1.x, b1.y, b1.z, b1.w};
#pragma unroll
            for (int i = 0; i < 8; ++i)
#pragma unroll
                for (int j = 0; j < 8; ++j)
                    acc[i][j] = fmaf(a[i], b[j], acc[i][j]);
        }
    }

    // Epilogue: apply mask + bias, store two float4 per row.
#pragma unroll
    for (int i = 0; i < 8; ++i) {
        int lr = (i < 4) ? (4 * ty + i) : (64 + 4 * ty + (i - 4));
        int r  = row0 + lr;
        if (r < N) {
            float m = g_mask[r] ? 1.0f : 0.0f;   // fma(acc, m, bo): exact bo when m=0
            float4 o0, o1;
            o0.x = fmaf(acc[i][0], m, boS[4 * tx + 0]);
            o0.y = fmaf(acc[i][1], m, boS[4 * tx + 1]);
            o0.z = fmaf(acc[i][2], m, boS[4 * tx + 2]);
            o0.w = fmaf(acc[i][3], m, boS[4 * tx + 3]);
            o1.x = fmaf(acc[i][4], m, boS[64 + 4 * tx + 0]);
            o1.y = fmaf(acc[i][5], m, boS[64 + 4 * tx + 1]);
            o1.z = fmaf(acc[i][6], m, boS[64 + 4 * tx + 2]);
            o1.w = fmaf(acc[i][7], m, boS[64 + 4 * tx + 3]);
            *(float4*)&out[r * DIM + 4 * tx]      = o0;
            *(float4*)&out[r * DIM + 64 + 4 * tx] = o1;
        }
    }
}

// ---------------------------------------------------------------------------
extern "C" void kernel_launch(void* const* d_in, const int* in_sizes, int n_in,
                              void* d_out, int out_size) {
    const float* x          = (const float*)d_in[0];
    const int*   edge_index = (const int*)d_in[1];
    const float* Wv         = (const float*)d_in[5];
    const float* Wo         = (const float*)d_in[7];
    const float* bo         = (const float*)d_in[8];
    float*       out        = (float*)d_out;

    const int N = in_sizes[0] / DIM;
    const int E = in_sizes[1] / 2;

    cudaFuncSetAttribute(out_kernel, cudaFuncAttributeMaxDynamicSharedMemorySize,
                         SMEM_BYTES);

    prep_kernel<<<DIM, DIM>>>(Wo, Wv, N);
    mask_kernel<<<(E + 255) / 256, 256>>>(edge_index + E, E);  // tgt = edge_index[1]
    out_kernel<<<(N + DIM - 1) / DIM, 256, SMEM_BYTES>>>(x, bo, out, N);
}

// round 3
// speedup vs baseline: 1.9400x; 1.9400x over previous
#include <cuda_runtime.h>
#include <cuda_fp16.h>
#include <cstdint>

#define DIM 128

// ---------------------------------------------------------------------------
// Global scratch (no allocations allowed)
// ---------------------------------------------------------------------------
__device__ __align__(16) __half g_Bc[DIM * DIM];   // Mc = Wo@Wv, fp16, row-major [n][k]
__device__ unsigned char g_mask[131072];

__device__ __forceinline__ uint32_t smem_u32(const void* p) {
    uint32_t a;
    asm("{ .reg .u64 t; cvta.to.shared.u64 t, %1; cvt.u32.u64 %0, t; }" : "=r"(a) : "l"(p));
    return a;
}
__device__ __forceinline__ void ldsm4(uint32_t& r0, uint32_t& r1, uint32_t& r2,
                                      uint32_t& r3, uint32_t a) {
    asm volatile("ldmatrix.sync.aligned.m8n8.x4.shared.b16 {%0,%1,%2,%3}, [%4];"
                 : "=r"(r0), "=r"(r1), "=r"(r2), "=r"(r3) : "r"(a));
}
__device__ __forceinline__ void mma16816(float* c, const uint32_t* a, const uint32_t* b) {
    asm volatile(
        "mma.sync.aligned.m16n8k16.row.col.f32.f16.f16.f32 "
        "{%0,%1,%2,%3},{%4,%5,%6,%7},{%8,%9},{%0,%1,%2,%3};"
        : "+f"(c[0]), "+f"(c[1]), "+f"(c[2]), "+f"(c[3])
        : "r"(a[0]), "r"(a[1]), "r"(a[2]), "r"(a[3]), "r"(b[0]), "r"(b[1]));
}

// ---------------------------------------------------------------------------
// Kernel 1: Mc = Wo @ Wv -> fp16, 4-way k-split per output; clear mask.
// grid 512 x 128. block b: row i = b>>2, j-range (b&3)*32.
// ---------------------------------------------------------------------------
__global__ void prep_kernel(const float* __restrict__ Wo,
                            const float* __restrict__ Wv, int N) {
    __shared__ float WoS[DIM];
    const int b = blockIdx.x;
    const int i = b >> 2;
    const int jb = (b & 3) * 32;
    const int tid = threadIdx.x;
    WoS[tid] = Wo[i * DIM + tid];
    __syncthreads();

    const int j = jb + (tid >> 2);
    const int kl = tid & 3;           // k-split lane
    float a0 = 0.f, a1 = 0.f, a2 = 0.f, a3 = 0.f;
#pragma unroll
    for (int kk = 0; kk < 32; kk += 4) {
        int k = kl * 32 + kk;
        a0 = fmaf(WoS[k + 0], Wv[(k + 0) * DIM + j], a0);
        a1 = fmaf(WoS[k + 1], Wv[(k + 1) * DIM + j], a1);
        a2 = fmaf(WoS[k + 2], Wv[(k + 2) * DIM + j], a2);
        a3 = fmaf(WoS[k + 3], Wv[(k + 3) * DIM + j], a3);
    }
    float acc = (a0 + a1) + (a2 + a3);
    acc += __shfl_xor_sync(0xffffffffu, acc, 1);
    acc += __shfl_xor_sync(0xffffffffu, acc, 2);
    if (kl == 0) g_Bc[i * DIM + j] = __float2half_rn(acc);

    int idx = b * 128 + tid;
    if (idx < N) g_mask[idx] = 0;
}

// ---------------------------------------------------------------------------
// Kernel 2: mask[tgt[e]] = 1, 4 edges per thread via int4.
// ---------------------------------------------------------------------------
__global__ void mask_kernel(const int* __restrict__ tgt, int E4) {
    int t = blockIdx.x * blockDim.x + threadIdx.x;
    if (t < E4) {
        int4 v = ((const int4*)tgt)[t];
        g_mask[v.x] = 1; g_mask[v.y] = 1; g_mask[v.z] = 1; g_mask[v.w] = 1;
    }
}

// ---------------------------------------------------------------------------
// Kernel 3: fp16 mma.sync GEMM, out = mask ? x @ Mc^T + bo : bo
// CTA: 128 rows x 128 cols, 8 warps (4x2), warp tile 32x64, mma m16n8k16.
// A/B in smem as fp16 rows padded to 272B (conflict-free ldmatrix).
// ---------------------------------------------------------------------------
#define ROWB   272                     // bytes per padded fp16 row (128*2 + 16)
#define AS_OFF 0                       // 128*272 = 34816
#define BS_OFF 34816                   // 128*272 = 34816
#define BO_OFF 69632                   // 512 B
#define SMEM_SZ 70400
// epilogue staging Ds (float, stride 132) reuses [0, 67584) after mainloop

__global__ __launch_bounds__(256) void gemm_kernel(const float* __restrict__ X,
                                                   const float* __restrict__ bo,
                                                   float* __restrict__ out, int Nn) {
    extern __shared__ unsigned char sm[];
    const int tid = threadIdx.x;
    const int warp = tid >> 5, lane = tid & 31;
    const int wm = warp & 3, wn = warp >> 2;        // warp tile: rows wm*32, cols wn*64
    const int gid = lane >> 2, tig = lane & 3;
    const uint32_t smb = smem_u32(sm);
    const int m0 = blockIdx.x * DIM;

    // B: copy g_Bc (32KB, L2-broadcast) into padded smem rows
    {
        const uint4* src = (const uint4*)g_Bc;
#pragma unroll
        for (int i = tid; i < 2048; i += 256) {
            int r = i >> 4, seg = i & 15;
            *(uint4*)(sm + BS_OFF + r * ROWB + seg * 16) = src[i];
        }
    }
    if (tid < DIM) ((float*)(sm + BO_OFF))[tid] = bo[tid];

    // A: load x fp32 -> fp16, padded rows
#pragma unroll
    for (int it = 0; it < 16; ++it) {
        int f = tid + 256 * it;            // 0..4095
        int r = f >> 5;                    // row
        int c4 = (f & 31) << 2;            // col (x4)
        float4 v = make_float4(0.f, 0.f, 0.f, 0.f);
        int grow = m0 + r;
        if (grow < Nn) v = *(const float4*)&X[grow * DIM + c4];
        __half2 h01 = __float22half2_rn(make_float2(v.x, v.y));
        __half2 h23 = __float22half2_rn(make_float2(v.z, v.w));
        uint2 w;
        w.x = *(uint32_t*)&h01; w.y = *(uint32_t*)&h23;
        *(uint2*)(sm + AS_OFF + r * ROWB + c4 * 2) = w;
    }
    __syncthreads();

    // Mainloop: 8 k-steps of 16
    float acc[2][8][4];
#pragma unroll
    for (int mt = 0; mt < 2; ++mt)
#pragma unroll
        for (int nt = 0; nt < 8; ++nt)
#pragma unroll
            for (int q = 0; q < 4; ++q) acc[mt][nt][q] = 0.f;

    const uint32_t lrow = lane & 15;
    const uint32_t lk16 = (lane >> 4) * 16;
#pragma unroll
    for (int kk = 0; kk < 8; ++kk) {
        uint32_t af[2][4];
#pragma unroll
        for (int mt = 0; mt < 2; ++mt) {
            uint32_t a = smb + AS_OFF + (wm * 32 + mt * 16 + lrow) * ROWB + kk * 32 + lk16;
            ldsm4(af[mt][0], af[mt][1], af[mt][2], af[mt][3], a);
        }
        uint32_t bf[8][2];
#pragma unroll
        for (int np = 0; np < 4; ++np) {
            uint32_t a = smb + BS_OFF + (wn * 64 + np * 16 + lrow) * ROWB + kk * 32 + lk16;
            uint32_t r0, r1, r2, r3;
            ldsm4(r0, r1, r2, r3, a);
            bf[2 * np][0] = r0; bf[2 * np + 1][0] = r1;
            bf[2 * np][1] = r2; bf[2 * np + 1][1] = r3;
        }
#pragma unroll
        for (int mt = 0; mt < 2; ++mt)
#pragma unroll
            for (int nt = 0; nt < 8; ++nt)
                mma16816(acc[mt][nt], af[mt], bf[nt]);
    }
    __syncthreads();   // all ldmatrix reads done before Ds overwrite

    // Stage to smem (fp32, stride 132) for coalesced masked store
    float* Ds = (float*)sm;
#pragma unroll
    for (int mt = 0; mt < 2; ++mt)
#pragma unroll
        for (int nt = 0; nt < 8; ++nt) {
            int r0 = wm * 32 + mt * 16 + gid;
            int col = wn * 64 + nt * 8 + 2 * tig;
            *(float2*)&Ds[r0 * 132 + col] = make_float2(acc[mt][nt][0], acc[mt][nt][1]);
            *(float2*)&Ds[(r0 + 8) * 132 + col] = make_float2(acc[mt][nt][2], acc[mt][nt][3]);
        }
    __syncthreads();

    const float* boS = (const float*)(sm + BO_OFF);
#pragma unroll
    for (int it = 0; it < 16; ++it) {
        int f = tid + 256 * it;
        int r = f >> 5;
        int c = (f & 31) << 2;
        int grow = m0 + r;
        if (grow < Nn) {
            float m = g_mask[grow] ? 1.0f : 0.0f;
            float4 d = *(const float4*)&Ds[r * 132 + c];
            float4 o;
            o.x = fmaf(d.x, m, boS[c + 0]);
            o.y = fmaf(d.y, m, boS[c + 1]);
            o.z = fmaf(d.z, m, boS[c + 2]);
            o.w = fmaf(d.w, m, boS[c + 3]);
            *(float4*)&out[grow * DIM + c] = o;
        }
    }
}

// ---------------------------------------------------------------------------
extern "C" void kernel_launch(void* const* d_in, const int* in_sizes, int n_in,
                              void* d_out, int out_size) {
    const float* x          = (const float*)d_in[0];
    const int*   edge_index = (const int*)d_in[1];
    const float* Wv         = (const float*)d_in[5];
    const float* Wo         = (const float*)d_in[7];
    const float* bo         = (const float*)d_in[8];
    float*       out        = (float*)d_out;

    const int N = in_sizes[0] / DIM;
    const int E = in_sizes[1] / 2;
    const int E4 = E / 4;

    cudaFuncSetAttribute(gemm_kernel, cudaFuncAttributeMaxDynamicSharedMemorySize,
                         SMEM_SZ);

    prep_kernel<<<512, 128>>>(Wo, Wv, N);
    mask_kernel<<<(E4 + 255) / 256, 256>>>(edge_index + E, E4);  // tgt = edge_index[1]
    gemm_kernel<<<(N + DIM - 1) / DIM, 256, SMEM_SZ>>>(x, bo, out, N);
}